// round 13
// baseline (speedup 1.0000x reference)
#include <cuda_runtime.h>
#include <cstdint>

#define NN 50000
#define C 128
#define EE 600000
#define SCAN_NB 196   // (NN + 255) / 256

// ---------------- device scratch ----------------
__device__ float    g_A[NN * C];
__device__ float    g_B[NN * C];
__device__ float    g_deg[NN];
__device__ unsigned g_Xs[NN * C];        // X split: per row 128 u32 (8 chunks x [h0 h1 l0 l1])
__device__ unsigned g_Hs[NN * C];        // H split
__device__ unsigned g_Rs[NN * C];        // (s*R + deg*c) split
__device__ unsigned g_Wf[2][2][16384];   // AB weights, fragment-order [layer][half]
__device__ unsigned g_Wbf[2][16384];     // OUT weights, fragment-order [layer]
__device__ int      g_cnt[NN];
__device__ int      g_rowp[NN + 1];
__device__ int      g_offw[NN];
__device__ int      g_bsum[256];
__device__ int      g_boff[256];
__device__ int      g_csr[EE];
__device__ int      g_is64;
__device__ float    g_s[2][C];
__device__ float    g_c[2][C];

// ---------------- helpers ----------------
__device__ __forceinline__ unsigned pack_bf(float hi, float lo) {
    unsigned r; asm("cvt.rn.bf16x2.f32 %0, %1, %2;" : "=r"(r) : "f"(hi), "f"(lo)); return r;
}
__device__ __forceinline__ void mma16(float* c, unsigned a0, unsigned a1, unsigned a2, unsigned a3,
                                      unsigned b0, unsigned b1) {
    asm volatile("mma.sync.aligned.m16n8k16.row.col.f32.bf16.bf16.f32 "
                 "{%0,%1,%2,%3},{%4,%5,%6,%7},{%8,%9},{%0,%1,%2,%3};"
                 : "+f"(c[0]), "+f"(c[1]), "+f"(c[2]), "+f"(c[3])
                 : "r"(a0), "r"(a1), "r"(a2), "r"(a3), "r"(b0), "r"(b1));
}
__device__ __forceinline__ void ldsm4(unsigned& r0, unsigned& r1, unsigned& r2, unsigned& r3,
                                      unsigned addr) {
    asm volatile("ldmatrix.sync.aligned.m8n8.x4.shared.b16 {%0,%1,%2,%3}, [%4];"
                 : "=r"(r0), "=r"(r1), "=r"(r2), "=r"(r3) : "r"(addr));
}
__device__ __forceinline__ unsigned smem_u32(const void* p) {
    unsigned a;
    asm("{ .reg .u64 t; cvta.to.shared.u64 t, %1; cvt.u32.u64 %0, t; }" : "=r"(a) : "l"(p));
    return a;
}
__device__ __forceinline__ void split2(float x0, float x1, unsigned& h, unsigned& l) {
    h = pack_bf(x1, x0);
    float lo0 = __uint_as_float(h << 16);
    float hi1 = __uint_as_float(h & 0xFFFF0000u);
    l = pack_bf(x1 - hi1, x0 - lo0);
}
__device__ __forceinline__ int edge_val(const void* ei, int idx) {
    if (g_is64) return (int)((const long long*)ei)[idx];
    return ((const int*)ei)[idx];
}
// split-array offset of the hi-u32 for pair index P (0..63) within a row
__device__ __forceinline__ int pair_off_h(int P) {
    return (P >> 3) * 16 + ((P >> 2) & 1) * 4 + (P & 3);
}
// fragment-order flat u32 offset (uint4 granule) for row, pair-in-chunk s, chunk kc
__device__ __forceinline__ int frag_base(int row, int kc, int s) {
    int n0g = row >> 5, q = (row >> 3) & 3, g8 = row & 7, tig = s & 3;
    return ((((kc * 4 + n0g) * 4 + q) * 8 + g8) * 4 + tig) * 4;
}

// ---------------- prep: zero cnt + fragment-order weights + BN affine ------
__global__ void prep_all(const float* __restrict__ w1a, const float* __restrict__ w2a,
                         const float* __restrict__ w1b, const float* __restrict__ w2b,
                         const float* g1, const float* be1, const float* rm1, const float* rv1,
                         const float* g2, const float* be2, const float* rm2, const float* rv2) {
    int gid = blockIdx.x * blockDim.x + threadIdx.x;   // 65536
    if (gid < NN) g_cnt[gid] = 0;
    if (gid < 2 * 256 * 64) {    // Wc pairs: layer, r(0..255), p(0..63)
        int layer = gid >> 14;
        int r = (gid >> 6) & 255;
        int p = gid & 63;
        const float* wa = layer ? w2a : w1a;
        int k0 = 2 * p, k1 = 2 * p + 1;
        float v0, v1;
        if (r < C) {
            v0 = wa[r * 2 * C + k0] - wa[r * 2 * C + C + k0];
            v1 = wa[r * 2 * C + k1] - wa[r * 2 * C + C + k1];
        } else {
            v0 = wa[(r - C) * 2 * C + C + k0];
            v1 = wa[(r - C) * 2 * C + C + k1];
        }
        unsigned h, l; split2(v0, v1, h, l);
        int half = r >> 7, row = r & 127;
        int kc = p >> 3, s = p & 7;
        int base = frag_base(row, kc, s);
        int chi = s >> 2;                       // 0 -> c0/c2, 1 -> c1/c3
        g_Wf[layer][half][base + chi] = h;
        g_Wf[layer][half][base + 2 + chi] = l;
    }
    if (gid < 2 * 128 * 64) {    // Wb pairs
        int layer = gid >> 13;
        int r = (gid >> 6) & 127;
        int p = gid & 63;
        const float* wb = layer ? w2b : w1b;
        float v0 = wb[r * C + 2 * p], v1 = wb[r * C + 2 * p + 1];
        unsigned h, l; split2(v0, v1, h, l);
        int kc = p >> 3, s = p & 7;
        int base = frag_base(r, kc, s);
        int chi = s >> 2;
        g_Wbf[layer][base + chi] = h;
        g_Wbf[layer][base + 2 + chi] = l;
    }
    if (gid < 256) {
        int layer = gid >> 7;
        int k = gid & 127;
        const float* g  = layer ? g2  : g1;
        const float* be = layer ? be2 : be1;
        const float* rm = layer ? rm2 : rm1;
        const float* rv = layer ? rv2 : rv1;
        float s = g[k] * rsqrtf(rv[k] + 1e-5f);
        g_s[layer][k] = s;
        g_c[layer][k] = be[k] - rm[k] * s;
    }
}

// ---------------- X -> split ----------------
__global__ void conv_x(const float* __restrict__ x) {
    int t = blockIdx.x * blockDim.x + threadIdx.x;   // NN*8
    if (t >= NN * 8) return;
    int r = t >> 3, kc = t & 7;
    const float* xr = x + (size_t)r * C + kc * 16;
    unsigned* o = g_Xs + (size_t)r * C + kc * 16;
    uint4 h0, h1, l0, l1;
    float4 a = *(const float4*)(xr + 0);
    float4 b = *(const float4*)(xr + 4);
    float4 cc = *(const float4*)(xr + 8);
    float4 d = *(const float4*)(xr + 12);
    split2(a.x, a.y, h0.x, l0.x);
    split2(a.z, a.w, h0.y, l0.y);
    split2(b.x, b.y, h0.z, l0.z);
    split2(b.z, b.w, h0.w, l0.w);
    split2(cc.x, cc.y, h1.x, l1.x);
    split2(cc.z, cc.w, h1.y, l1.y);
    split2(d.x, d.y, h1.z, l1.z);
    split2(d.z, d.w, h1.w, l1.w);
    *(uint4*)(o + 0)  = h0;
    *(uint4*)(o + 4)  = h1;
    *(uint4*)(o + 8)  = l0;
    *(uint4*)(o + 12) = l1;
}

__global__ void detect_kernel(const void* __restrict__ ei) {
    int t = threadIdx.x;
    int bad = 0;
    if (t < 16) {
        long long v = ((const long long*)ei)[t];
        bad = (v < 0) || (v >= (long long)NN);
    }
    unsigned m = __ballot_sync(0xFFFFFFFFu, bad);
    if (t == 0) g_is64 = (m == 0);
}

__global__ void hist_kernel(const void* __restrict__ ei) {
    int e = blockIdx.x * blockDim.x + threadIdx.x;
    if (e >= EE) return;
    atomicAdd(&g_cnt[edge_val(ei, EE + e)], 1);
}

__global__ void scan_local() {
    __shared__ int sm[256];
    int t = threadIdx.x;
    int i = blockIdx.x * 256 + t;
    int v = (i < NN) ? g_cnt[i] : 0;
    sm[t] = v;
    __syncthreads();
#pragma unroll
    for (int off = 1; off < 256; off <<= 1) {
        int u = (t >= off) ? sm[t - off] : 0;
        __syncthreads();
        sm[t] += u;
        __syncthreads();
    }
    if (i < NN) g_rowp[i] = sm[t] - v;
    if (t == 255) g_bsum[blockIdx.x] = sm[255];
}

__global__ void scan_bsum() {
    __shared__ int sm[256];
    int t = threadIdx.x;
    int v = (t < SCAN_NB) ? g_bsum[t] : 0;
    sm[t] = v;
    __syncthreads();
#pragma unroll
    for (int off = 1; off < 256; off <<= 1) {
        int u = (t >= off) ? sm[t - off] : 0;
        __syncthreads();
        sm[t] += u;
        __syncthreads();
    }
    g_boff[t] = sm[t] - v;
    if (t == 255) g_rowp[NN] = sm[255];
}

__global__ void scan_add() {
    int i = blockIdx.x * 256 + threadIdx.x;
    if (i >= NN) return;
    int r = g_rowp[i] + g_boff[blockIdx.x];
    g_rowp[i] = r;
    g_offw[i] = r;
}

__global__ void scatter_kernel(const void* __restrict__ ei) {
    int e = blockIdx.x * blockDim.x + threadIdx.x;
    if (e >= EE) return;
    int d = edge_val(ei, EE + e);
    int s = edge_val(ei, e);
    int p = atomicAdd(&g_offw[d], 1);
    g_csr[p] = s;
}

// ---------------- bf16 MMA GEMM: A via smem+LDSM, W via fragment LDG -------
// A smem: merged hi/lo rows of 16 u32, chunk swizzle c' = c ^ ((row>>1)&3),
// double-buffered, ONE barrier per k-chunk.
// mode 0: AB (out g_A with ba / g_B, by grid.y); mode 1: OUT plain -> Og (+deg*bias);
// mode 2: OUT fused relu+L2norm -> g_Hs (split)
__global__ __launch_bounds__(256) void mma_gemm(
    const unsigned* __restrict__ Xs, const unsigned* __restrict__ Wfrag,
    const float* __restrict__ bias, float* __restrict__ Og, int mode)
{
    __shared__ unsigned As[2][2048];
    __shared__ float rowss[128];

    int tid = threadIdx.x;
    int i0 = blockIdx.x * 128;
    int half = blockIdx.y;

    if (tid < 128) rowss[tid] = 0.f;

    // A loader: 2 threads per row; thread covers chunks cq, cq+1 (16B each)
    int lrow = tid >> 1;
    int cq = (tid & 1) * 2;
    int gi = i0 + lrow;
    const unsigned* xr = Xs + (size_t)gi * C;
    int sA = (lrow >> 1) & 3;
    unsigned so0 = lrow * 16 + ((cq    ) ^ sA) * 4;
    unsigned so1 = lrow * 16 + ((cq + 1) ^ sA) * 4;

    int wid = tid >> 5, lane = tid & 31;
    int gid = lane >> 2, tig = lane & 3;
    int m0 = (wid & 1) * 64;
    int n0g = wid >> 1;
    int n0 = n0g * 32;

    // W fragment pointer: lane-coalesced uint4 stream
    const uint4* wf = (const uint4*)(Wfrag + (mode == 0 ? half * 16384 : 0))
                      + (n0g * 128 + gid * 4 + tig);

    // ldmatrix per-lane A addresses (loop-invariant; swizzle folded in)
    unsigned aBase = smem_u32(&As[0][0]);
    int mat = lane >> 3, mr = lane & 7;
    unsigned aoff[8];
#pragma unroll
    for (int mt = 0; mt < 4; mt++) {
#pragma unroll
        for (int p = 0; p < 2; p++) {                 // 0 = hi, 1 = lo
            int row = m0 + mt * 16 + (mat & 1) * 8 + mr;
            int c = p * 2 + (mat >> 1);
            int sr = (row >> 1) & 3;
            aoff[mt * 2 + p] = (unsigned)((row * 16 + ((c ^ sr) << 2)) * 4);
        }
    }

    float acc[4][4][4];
#pragma unroll
    for (int a = 0; a < 4; a++)
#pragma unroll
        for (int b = 0; b < 4; b++)
#pragma unroll
            for (int d = 0; d < 4; d++) acc[a][b][d] = 0.f;

    uint4 xa0, xa1;
    if (gi < NN) {
        xa0 = *(const uint4*)(xr + cq * 4);
        xa1 = *(const uint4*)(xr + cq * 4 + 4);
    } else { xa0 = make_uint4(0,0,0,0); xa1 = xa0; }

    for (int kc = 0; kc < 8; kc++) {
        int st = kc & 1;
        unsigned* aS = As[st];
        *(uint4*)&aS[so0] = xa0;
        *(uint4*)&aS[so1] = xa1;
        __syncthreads();

        if (kc < 7) {
            int gk = (kc + 1) * 16 + cq * 4;
            if (gi < NN) {
                xa0 = *(const uint4*)(xr + gk);
                xa1 = *(const uint4*)(xr + gk + 4);
            }
        }

        // B fragments: 4 coalesced LDG.128 (chunk stride 512 uint4, q stride 32)
        unsigned bh0[4], bh1[4], bl0[4], bl1[4];
#pragma unroll
        for (int q = 0; q < 4; q++) {
            uint4 v = wf[kc * 512 + q * 32];
            bh0[q] = v.x; bh1[q] = v.y; bl0[q] = v.z; bl1[q] = v.w;
        }

        unsigned ab = aBase + st * 8192;
#pragma unroll
        for (int mt = 0; mt < 4; mt++) {
            unsigned ah0, ah1, ah2, ah3, al0, al1, al2, al3;
            ldsm4(ah0, ah1, ah2, ah3, ab + aoff[mt * 2]);
            ldsm4(al0, al1, al2, al3, ab + aoff[mt * 2 + 1]);
#pragma unroll
            for (int nt = 0; nt < 4; nt++) {
                mma16(acc[mt][nt], ah0, ah1, ah2, ah3, bh0[nt], bh1[nt]);
                mma16(acc[mt][nt], ah0, ah1, ah2, ah3, bl0[nt], bl1[nt]);
                mma16(acc[mt][nt], al0, al1, al2, al3, bh0[nt], bh1[nt]);
            }
        }
    }

    // --- epilogue ---
    if (mode == 0) {
        float* outp = half ? g_B : g_A;
#pragma unroll
        for (int mt = 0; mt < 4; mt++) {
            int r0 = i0 + m0 + mt * 16 + gid;
            int r1 = r0 + 8;
#pragma unroll
            for (int nt = 0; nt < 4; nt++) {
                int col = n0 + nt * 8 + 2 * tig;
                float* cc = acc[mt][nt];
                float b0 = 0.f, b1 = 0.f;
                if (half == 0) { b0 = bias[col]; b1 = bias[col + 1]; }
                if (r0 < NN) { float2 v = {cc[0] + b0, cc[1] + b1}; *(float2*)(outp + (size_t)r0 * C + col) = v; }
                if (r1 < NN) { float2 v = {cc[2] + b0, cc[3] + b1}; *(float2*)(outp + (size_t)r1 * C + col) = v; }
            }
        }
    } else if (mode == 1) {
#pragma unroll
        for (int mt = 0; mt < 4; mt++) {
            int r0 = i0 + m0 + mt * 16 + gid;
            int r1 = r0 + 8;
            float d0 = (r0 < NN) ? g_deg[r0] : 0.f;
            float d1 = (r1 < NN) ? g_deg[r1] : 0.f;
#pragma unroll
            for (int nt = 0; nt < 4; nt++) {
                int col = n0 + nt * 8 + 2 * tig;
                float* cc = acc[mt][nt];
                float bb0 = bias[col], bb1 = bias[col + 1];
                if (r0 < NN) { float2 v = {cc[0] + d0 * bb0, cc[1] + d0 * bb1}; *(float2*)(Og + (size_t)r0 * C + col) = v; }
                if (r1 < NN) { float2 v = {cc[2] + d1 * bb0, cc[3] + d1 * bb1}; *(float2*)(Og + (size_t)r1 * C + col) = v; }
            }
        }
    } else {
        // fused relu + L2 norm -> g_Hs (split pairs)
        __syncthreads();
#pragma unroll
        for (int mt = 0; mt < 4; mt++) {
            int r0 = i0 + m0 + mt * 16 + gid;
            int r1 = r0 + 8;
            int l0 = m0 + mt * 16 + gid, l1 = l0 + 8;
            float d0 = (r0 < NN) ? g_deg[r0] : 0.f;
            float d1 = (r1 < NN) ? g_deg[r1] : 0.f;
            float ss0 = 0.f, ss1 = 0.f;
#pragma unroll
            for (int nt = 0; nt < 4; nt++) {
                int col = n0 + nt * 8 + 2 * tig;
                float* cc = acc[mt][nt];
                float bb0 = bias[col], bb1 = bias[col + 1];
                cc[0] = fmaxf(cc[0] + d0 * bb0, 0.f);
                cc[1] = fmaxf(cc[1] + d0 * bb1, 0.f);
                cc[2] = fmaxf(cc[2] + d1 * bb0, 0.f);
                cc[3] = fmaxf(cc[3] + d1 * bb1, 0.f);
                ss0 += cc[0] * cc[0] + cc[1] * cc[1];
                ss1 += cc[2] * cc[2] + cc[3] * cc[3];
            }
            atomicAdd(&rowss[l0], ss0);
            atomicAdd(&rowss[l1], ss1);
        }
        __syncthreads();
#pragma unroll
        for (int mt = 0; mt < 4; mt++) {
            int r0 = i0 + m0 + mt * 16 + gid;
            int r1 = r0 + 8;
            int l0 = m0 + mt * 16 + gid, l1 = l0 + 8;
            float inv0 = 1.f / fmaxf(sqrtf(rowss[l0]), 1e-12f);
            float inv1 = 1.f / fmaxf(sqrtf(rowss[l1]), 1e-12f);
#pragma unroll
            for (int nt = 0; nt < 4; nt++) {
                int col = n0 + nt * 8 + 2 * tig;
                int P = (col >> 1);
                int off = pair_off_h(P);
                float* cc = acc[mt][nt];
                unsigned h, l;
                if (r0 < NN) {
                    split2(cc[0] * inv0, cc[1] * inv0, h, l);
                    g_Hs[(size_t)r0 * C + off] = h;
                    g_Hs[(size_t)r0 * C + off + 8] = l;
                }
                if (r1 < NN) {
                    split2(cc[2] * inv1, cc[3] * inv1, h, l);
                    g_Hs[(size_t)r1 * C + off] = h;
                    g_Hs[(size_t)r1 * C + off + 8] = l;
                }
            }
        }
    }
}

// ---------------- CSR edge aggregate + BN affine + split -------------------
__global__ __launch_bounds__(256) void edge_csr_kernel(int layer) {
    int node = (blockIdx.x * blockDim.x + threadIdx.x) >> 5;
    int lane = threadIdx.x & 31;
    if (node >= NN) return;
    int s0 = g_rowp[node], s1 = g_rowp[node + 1];
    float4 a = ((const float4*)(g_A + (size_t)node * C))[lane];
    float4 acc = make_float4(0.f, 0.f, 0.f, 0.f);
    int e = s0;
    for (; e + 3 < s1; e += 4) {
        int i0 = g_csr[e], i1 = g_csr[e + 1], i2 = g_csr[e + 2], i3 = g_csr[e + 3];
        float4 b0 = ((const float4*)(g_B + (size_t)i0 * C))[lane];
        float4 b1 = ((const float4*)(g_B + (size_t)i1 * C))[lane];
        float4 b2 = ((const float4*)(g_B + (size_t)i2 * C))[lane];
        float4 b3 = ((const float4*)(g_B + (size_t)i3 * C))[lane];
        acc.x += fmaxf(a.x + b0.x, 0.f) + fmaxf(a.x + b1.x, 0.f)
               + fmaxf(a.x + b2.x, 0.f) + fmaxf(a.x + b3.x, 0.f);
        acc.y += fmaxf(a.y + b0.y, 0.f) + fmaxf(a.y + b1.y, 0.f)
               + fmaxf(a.y + b2.y, 0.f) + fmaxf(a.y + b3.y, 0.f);
        acc.z += fmaxf(a.z + b0.z, 0.f) + fmaxf(a.z + b1.z, 0.f)
               + fmaxf(a.z + b2.z, 0.f) + fmaxf(a.z + b3.z, 0.f);
        acc.w += fmaxf(a.w + b0.w, 0.f) + fmaxf(a.w + b1.w, 0.f)
               + fmaxf(a.w + b2.w, 0.f) + fmaxf(a.w + b3.w, 0.f);
    }
    for (; e < s1; e++) {
        int sa = g_csr[e];
        float4 b0 = ((const float4*)(g_B + (size_t)sa * C))[lane];
        acc.x += fmaxf(a.x + b0.x, 0.f);
        acc.y += fmaxf(a.y + b0.y, 0.f);
        acc.z += fmaxf(a.z + b0.z, 0.f);
        acc.w += fmaxf(a.w + b0.w, 0.f);
    }
    float dg = (float)(s1 - s0);
    float4 sc = ((const float4*)(g_s[layer]))[lane];
    float4 cv = ((const float4*)(g_c[layer]))[lane];
    acc.x = sc.x * acc.x + dg * cv.x;
    acc.y = sc.y * acc.y + dg * cv.y;
    acc.z = sc.z * acc.z + dg * cv.z;
    acc.w = sc.w * acc.w + dg * cv.w;
    int P0 = lane * 2, P1 = lane * 2 + 1;
    int off0 = pair_off_h(P0), off1 = pair_off_h(P1);
    unsigned h, l;
    unsigned* o = g_Rs + (size_t)node * C;
    split2(acc.x, acc.y, h, l);
    o[off0] = h; o[off0 + 8] = l;
    split2(acc.z, acc.w, h, l);
    o[off1] = h; o[off1 + 8] = l;
    if (lane == 0) g_deg[node] = dg;
}

// ---------------- launch ----------------------------------------------------
extern "C" void kernel_launch(void* const* d_in, const int* in_sizes, int n_in,
                              void* d_out, int out_size) {
    const float* x   = (const float*)d_in[0];
    const void*  ei  = d_in[1];
    const float* w1a = (const float*)d_in[2];
    const float* b1a = (const float*)d_in[3];
    const float* g1  = (const float*)d_in[4];
    const float* be1 = (const float*)d_in[5];
    const float* rm1 = (const float*)d_in[6];
    const float* rv1 = (const float*)d_in[7];
    const float* w1b = (const float*)d_in[8];
    const float* b1b = (const float*)d_in[9];
    const float* w2a = (const float*)d_in[10];
    const float* b2a = (const float*)d_in[11];
    const float* g2  = (const float*)d_in[12];
    const float* be2 = (const float*)d_in[13];
    const float* rm2 = (const float*)d_in[14];
    const float* rv2 = (const float*)d_in[15];
    const float* w2b = (const float*)d_in[16];
    const float* b2b = (const float*)d_in[17];
    float* out = (float*)d_out;

    const int ROWB = (NN + 127) / 128;          // 391
    const int EB   = (NN * 32 + 255) / 256;     // 6250

    unsigned *Wf0, *Wf1, *Wbf0, *Wbf1;
    unsigned *Xs, *Hs, *Rs;
    cudaGetSymbolAddress((void**)&Xs, g_Xs);
    cudaGetSymbolAddress((void**)&Hs, g_Hs);
    cudaGetSymbolAddress((void**)&Rs, g_Rs);
    cudaGetSymbolAddress((void**)&Wf0, g_Wf);
    Wf1 = Wf0 + 2 * 16384;
    cudaGetSymbolAddress((void**)&Wbf0, g_Wbf);
    Wbf1 = Wbf0 + 16384;

    prep_all<<<256, 256>>>(w1a, w2a, w1b, w2b, g1, be1, rm1, rv1, g2, be2, rm2, rv2); // 0
    detect_kernel<<<1, 32>>>(ei);                                                     // 1
    conv_x<<<(NN * 8 + 255) / 256, 256>>>(x);                                         // 2
    // layer-1 AB GEMM at stream index 3 -> profiled by ncu
    mma_gemm<<<dim3(ROWB, 2), 256>>>(Xs, Wf0, b1a, nullptr, 0);                       // 3 -> g_A,g_B
    hist_kernel<<<(EE + 255) / 256, 256>>>(ei);                                       // 4
    scan_local<<<SCAN_NB, 256>>>();                                                   // 5
    scan_bsum<<<1, 256>>>();                                                          // 6
    scan_add<<<SCAN_NB, 256>>>();                                                     // 7
    scatter_kernel<<<(EE + 255) / 256, 256>>>(ei);                                    // 8

    // ---- layer 1 ----
    edge_csr_kernel<<<EB, 256>>>(0);                                                  // -> g_Rs,g_deg
    mma_gemm<<<dim3(ROWB, 1), 256>>>(Rs, Wbf0, b1b, nullptr, 2);                      // -> g_Hs

    // ---- layer 2 ----
    mma_gemm<<<dim3(ROWB, 2), 256>>>(Hs, Wf1, b2a, nullptr, 0);                       // g_Hs -> g_A,g_B
    edge_csr_kernel<<<EB, 256>>>(1);
    mma_gemm<<<dim3(ROWB, 1), 256>>>(Rs, Wbf1, b2b, out, 1);                          // -> d_out
}

// round 15
// speedup vs baseline: 1.2093x; 1.2093x over previous
#include <cuda_runtime.h>
#include <cstdint>

#define NN 50000
#define C 128
#define EE 600000
#define SCAN_NB 196   // (NN + 255) / 256

// ---------------- device scratch ----------------
__device__ float    g_A[NN * C];
__device__ float    g_B[NN * C];
__device__ float    g_deg[NN];
__device__ unsigned g_Xs[NN * C];        // X split: per row 128 u32 (8 chunks x [h0 h1 l0 l1])
__device__ unsigned g_Hs[NN * C];        // H split
__device__ unsigned g_Rs[NN * C];        // (s*R + deg*c) split
__device__ unsigned g_Wf[2][2][16384];   // AB weights, fragment-order [layer][half]
__device__ unsigned g_Wbf[2][16384];     // OUT weights, fragment-order [layer]
__device__ int      g_cnt[NN];
__device__ int      g_rowp[NN + 1];
__device__ int      g_offw[NN];
__device__ int      g_bsum[256];
__device__ int      g_boff[256];
__device__ int      g_csr[EE];
__device__ int      g_is64;
__device__ float    g_s[2][C];
__device__ float    g_c[2][C];

// ---------------- helpers ----------------
__device__ __forceinline__ unsigned pack_bf(float hi, float lo) {
    unsigned r; asm("cvt.rn.bf16x2.f32 %0, %1, %2;" : "=r"(r) : "f"(hi), "f"(lo)); return r;
}
__device__ __forceinline__ void mma16(float* c, unsigned a0, unsigned a1, unsigned a2, unsigned a3,
                                      unsigned b0, unsigned b1) {
    asm volatile("mma.sync.aligned.m16n8k16.row.col.f32.bf16.bf16.f32 "
                 "{%0,%1,%2,%3},{%4,%5,%6,%7},{%8,%9},{%0,%1,%2,%3};"
                 : "+f"(c[0]), "+f"(c[1]), "+f"(c[2]), "+f"(c[3])
                 : "r"(a0), "r"(a1), "r"(a2), "r"(a3), "r"(b0), "r"(b1));
}
__device__ __forceinline__ void ldsm4(unsigned& r0, unsigned& r1, unsigned& r2, unsigned& r3,
                                      unsigned addr) {
    asm volatile("ldmatrix.sync.aligned.m8n8.x4.shared.b16 {%0,%1,%2,%3}, [%4];"
                 : "=r"(r0), "=r"(r1), "=r"(r2), "=r"(r3) : "r"(addr));
}
__device__ __forceinline__ unsigned smem_u32(const void* p) {
    unsigned a;
    asm("{ .reg .u64 t; cvta.to.shared.u64 t, %1; cvt.u32.u64 %0, t; }" : "=r"(a) : "l"(p));
    return a;
}
__device__ __forceinline__ void split2(float x0, float x1, unsigned& h, unsigned& l) {
    h = pack_bf(x1, x0);
    float lo0 = __uint_as_float(h << 16);
    float hi1 = __uint_as_float(h & 0xFFFF0000u);
    l = pack_bf(x1 - hi1, x0 - lo0);
}
__device__ __forceinline__ int edge_val(const void* ei, int idx) {
    if (g_is64) return (int)((const long long*)ei)[idx];
    return ((const int*)ei)[idx];
}
// split-array offset of the hi-u32 for pair index P (0..63) within a row
__device__ __forceinline__ int pair_off_h(int P) {
    return (P >> 3) * 16 + ((P >> 2) & 1) * 4 + (P & 3);
}
// fragment-order flat u32 offset (uint4 granule) for row, pair-in-chunk s, chunk kc
__device__ __forceinline__ int frag_base(int row, int kc, int s) {
    int n0g = row >> 5, q = (row >> 3) & 3, g8 = row & 7, tig = s & 3;
    return ((((kc * 4 + n0g) * 4 + q) * 8 + g8) * 4 + tig) * 4;
}

// ---------------- prep: zero cnt + fragment-order weights + BN affine ------
__global__ void prep_all(const float* __restrict__ w1a, const float* __restrict__ w2a,
                         const float* __restrict__ w1b, const float* __restrict__ w2b,
                         const float* g1, const float* be1, const float* rm1, const float* rv1,
                         const float* g2, const float* be2, const float* rm2, const float* rv2) {
    int gid = blockIdx.x * blockDim.x + threadIdx.x;   // 65536
    if (gid < NN) g_cnt[gid] = 0;
    if (gid < 2 * 256 * 64) {    // Wc pairs: layer, r(0..255), p(0..63)
        int layer = gid >> 14;
        int r = (gid >> 6) & 255;
        int p = gid & 63;
        const float* wa = layer ? w2a : w1a;
        int k0 = 2 * p, k1 = 2 * p + 1;
        float v0, v1;
        if (r < C) {
            v0 = wa[r * 2 * C + k0] - wa[r * 2 * C + C + k0];
            v1 = wa[r * 2 * C + k1] - wa[r * 2 * C + C + k1];
        } else {
            v0 = wa[(r - C) * 2 * C + C + k0];
            v1 = wa[(r - C) * 2 * C + C + k1];
        }
        unsigned h, l; split2(v0, v1, h, l);
        int half = r >> 7, row = r & 127;
        int kc = p >> 3, s = p & 7;
        int base = frag_base(row, kc, s);
        int chi = s >> 2;                       // 0 -> c0/c2, 1 -> c1/c3
        g_Wf[layer][half][base + chi] = h;
        g_Wf[layer][half][base + 2 + chi] = l;
    }
    if (gid < 2 * 128 * 64) {    // Wb pairs
        int layer = gid >> 13;
        int r = (gid >> 6) & 127;
        int p = gid & 63;
        const float* wb = layer ? w2b : w1b;
        float v0 = wb[r * C + 2 * p], v1 = wb[r * C + 2 * p + 1];
        unsigned h, l; split2(v0, v1, h, l);
        int kc = p >> 3, s = p & 7;
        int base = frag_base(r, kc, s);
        int chi = s >> 2;
        g_Wbf[layer][base + chi] = h;
        g_Wbf[layer][base + 2 + chi] = l;
    }
    if (gid < 256) {
        int layer = gid >> 7;
        int k = gid & 127;
        const float* g  = layer ? g2  : g1;
        const float* be = layer ? be2 : be1;
        const float* rm = layer ? rm2 : rm1;
        const float* rv = layer ? rv2 : rv1;
        float s = g[k] * rsqrtf(rv[k] + 1e-5f);
        g_s[layer][k] = s;
        g_c[layer][k] = be[k] - rm[k] * s;
    }
}

// ---------------- X -> split ----------------
__global__ void conv_x(const float* __restrict__ x) {
    int t = blockIdx.x * blockDim.x + threadIdx.x;   // NN*8
    if (t >= NN * 8) return;
    int r = t >> 3, kc = t & 7;
    const float* xr = x + (size_t)r * C + kc * 16;
    unsigned* o = g_Xs + (size_t)r * C + kc * 16;
    uint4 h0, h1, l0, l1;
    float4 a = *(const float4*)(xr + 0);
    float4 b = *(const float4*)(xr + 4);
    float4 cc = *(const float4*)(xr + 8);
    float4 d = *(const float4*)(xr + 12);
    split2(a.x, a.y, h0.x, l0.x);
    split2(a.z, a.w, h0.y, l0.y);
    split2(b.x, b.y, h0.z, l0.z);
    split2(b.z, b.w, h0.w, l0.w);
    split2(cc.x, cc.y, h1.x, l1.x);
    split2(cc.z, cc.w, h1.y, l1.y);
    split2(d.x, d.y, h1.z, l1.z);
    split2(d.z, d.w, h1.w, l1.w);
    *(uint4*)(o + 0)  = h0;
    *(uint4*)(o + 4)  = h1;
    *(uint4*)(o + 8)  = l0;
    *(uint4*)(o + 12) = l1;
}

__global__ void detect_kernel(const void* __restrict__ ei) {
    int t = threadIdx.x;
    int bad = 0;
    if (t < 16) {
        long long v = ((const long long*)ei)[t];
        bad = (v < 0) || (v >= (long long)NN);
    }
    unsigned m = __ballot_sync(0xFFFFFFFFu, bad);
    if (t == 0) g_is64 = (m == 0);
}

__global__ void hist_kernel(const void* __restrict__ ei) {
    int e = blockIdx.x * blockDim.x + threadIdx.x;
    if (e >= EE) return;
    atomicAdd(&g_cnt[edge_val(ei, EE + e)], 1);
}

__global__ void scan_local() {
    __shared__ int sm[256];
    int t = threadIdx.x;
    int i = blockIdx.x * 256 + t;
    int v = (i < NN) ? g_cnt[i] : 0;
    sm[t] = v;
    __syncthreads();
#pragma unroll
    for (int off = 1; off < 256; off <<= 1) {
        int u = (t >= off) ? sm[t - off] : 0;
        __syncthreads();
        sm[t] += u;
        __syncthreads();
    }
    if (i < NN) g_rowp[i] = sm[t] - v;
    if (t == 255) g_bsum[blockIdx.x] = sm[255];
}

__global__ void scan_bsum() {
    __shared__ int sm[256];
    int t = threadIdx.x;
    int v = (t < SCAN_NB) ? g_bsum[t] : 0;
    sm[t] = v;
    __syncthreads();
#pragma unroll
    for (int off = 1; off < 256; off <<= 1) {
        int u = (t >= off) ? sm[t - off] : 0;
        __syncthreads();
        sm[t] += u;
        __syncthreads();
    }
    g_boff[t] = sm[t] - v;
    if (t == 255) g_rowp[NN] = sm[255];
}

__global__ void scan_add() {
    int i = blockIdx.x * 256 + threadIdx.x;
    if (i >= NN) return;
    int r = g_rowp[i] + g_boff[blockIdx.x];
    g_rowp[i] = r;
    g_offw[i] = r;
}

__global__ void scatter_kernel(const void* __restrict__ ei) {
    int e = blockIdx.x * blockDim.x + threadIdx.x;
    if (e >= EE) return;
    int d = edge_val(ei, EE + e);
    int s = edge_val(ei, e);
    int p = atomicAdd(&g_offw[d], 1);
    g_csr[p] = s;
}

// ---------------- bf16 MMA GEMM: A via smem+LDSM, W via fragment LDG -------
// A smem: merged hi/lo rows of 16 u32, chunk swizzle c' = c ^ ((row>>1)&3),
// double-buffered, ONE barrier per k-chunk. __launch_bounds__(256,2) pins
// regs <= 128 so 2 CTAs/SM fit (R13 regression root cause: 130 regs -> 1 CTA).
// mode 0: AB (out g_A with ba / g_B, by grid.y); mode 1: OUT plain -> Og (+deg*bias);
// mode 2: OUT fused relu+L2norm -> g_Hs (split)
__global__ __launch_bounds__(256, 2) void mma_gemm(
    const unsigned* __restrict__ Xs, const unsigned* __restrict__ Wfrag,
    const float* __restrict__ bias, float* __restrict__ Og, int mode)
{
    __shared__ unsigned As[2][2048];
    __shared__ float rowss[128];

    int tid = threadIdx.x;
    int i0 = blockIdx.x * 128;
    int half = blockIdx.y;

    if (tid < 128) rowss[tid] = 0.f;

    // A loader: 2 threads per row; thread covers chunks cq, cq+1 (16B each)
    int lrow = tid >> 1;
    int cq = (tid & 1) * 2;
    int gi = i0 + lrow;
    const unsigned* xr = Xs + (size_t)gi * C;
    int sA = (lrow >> 1) & 3;
    unsigned so0 = lrow * 16 + ((cq    ) ^ sA) * 4;
    unsigned so1 = lrow * 16 + ((cq + 1) ^ sA) * 4;

    int wid = tid >> 5, lane = tid & 31;
    int gid = lane >> 2, tig = lane & 3;
    int m0 = (wid & 1) * 64;
    int n0g = wid >> 1;
    int n0 = n0g * 32;

    // W fragment pointer: lane-coalesced uint4 stream
    const uint4* wf = (const uint4*)(Wfrag + (mode == 0 ? half * 16384 : 0))
                      + (n0g * 128 + gid * 4 + tig);

    // ldmatrix per-lane A addresses (loop-invariant; swizzle folded in)
    unsigned aBase = smem_u32(&As[0][0]);
    int mat = lane >> 3, mr = lane & 7;
    unsigned aoff[8];
#pragma unroll
    for (int mt = 0; mt < 4; mt++) {
#pragma unroll
        for (int p = 0; p < 2; p++) {                 // 0 = hi, 1 = lo
            int row = m0 + mt * 16 + (mat & 1) * 8 + mr;
            int c = p * 2 + (mat >> 1);
            int sr = (row >> 1) & 3;
            aoff[mt * 2 + p] = (unsigned)((row * 16 + ((c ^ sr) << 2)) * 4);
        }
    }

    float acc[4][4][4];
#pragma unroll
    for (int a = 0; a < 4; a++)
#pragma unroll
        for (int b = 0; b < 4; b++)
#pragma unroll
            for (int d = 0; d < 4; d++) acc[a][b][d] = 0.f;

    uint4 xa0, xa1;
    if (gi < NN) {
        xa0 = *(const uint4*)(xr + cq * 4);
        xa1 = *(const uint4*)(xr + cq * 4 + 4);
    } else { xa0 = make_uint4(0,0,0,0); xa1 = xa0; }

    for (int kc = 0; kc < 8; kc++) {
        int st = kc & 1;
        unsigned* aS = As[st];
        *(uint4*)&aS[so0] = xa0;
        *(uint4*)&aS[so1] = xa1;
        __syncthreads();

        if (kc < 7) {
            int gk = (kc + 1) * 16 + cq * 4;
            if (gi < NN) {
                xa0 = *(const uint4*)(xr + gk);
                xa1 = *(const uint4*)(xr + gk + 4);
            }
        }

        // B fragments: 4 coalesced LDG.128 (chunk stride 512 uint4, q stride 32)
        unsigned bh0[4], bh1[4], bl0[4], bl1[4];
#pragma unroll
        for (int q = 0; q < 4; q++) {
            uint4 v = wf[kc * 512 + q * 32];
            bh0[q] = v.x; bh1[q] = v.y; bl0[q] = v.z; bl1[q] = v.w;
        }

        unsigned ab = aBase + st * 8192;
#pragma unroll
        for (int mt = 0; mt < 4; mt++) {
            unsigned ah0, ah1, ah2, ah3, al0, al1, al2, al3;
            ldsm4(ah0, ah1, ah2, ah3, ab + aoff[mt * 2]);
            ldsm4(al0, al1, al2, al3, ab + aoff[mt * 2 + 1]);
#pragma unroll
            for (int nt = 0; nt < 4; nt++) {
                mma16(acc[mt][nt], ah0, ah1, ah2, ah3, bh0[nt], bh1[nt]);
                mma16(acc[mt][nt], ah0, ah1, ah2, ah3, bl0[nt], bl1[nt]);
                mma16(acc[mt][nt], al0, al1, al2, al3, bh0[nt], bh1[nt]);
            }
        }
    }

    // --- epilogue ---
    if (mode == 0) {
        float* outp = half ? g_B : g_A;
#pragma unroll
        for (int mt = 0; mt < 4; mt++) {
            int r0 = i0 + m0 + mt * 16 + gid;
            int r1 = r0 + 8;
#pragma unroll
            for (int nt = 0; nt < 4; nt++) {
                int col = n0 + nt * 8 + 2 * tig;
                float* cc = acc[mt][nt];
                float b0 = 0.f, b1 = 0.f;
                if (half == 0) { b0 = bias[col]; b1 = bias[col + 1]; }
                if (r0 < NN) { float2 v = {cc[0] + b0, cc[1] + b1}; *(float2*)(outp + (size_t)r0 * C + col) = v; }
                if (r1 < NN) { float2 v = {cc[2] + b0, cc[3] + b1}; *(float2*)(outp + (size_t)r1 * C + col) = v; }
            }
        }
    } else if (mode == 1) {
#pragma unroll
        for (int mt = 0; mt < 4; mt++) {
            int r0 = i0 + m0 + mt * 16 + gid;
            int r1 = r0 + 8;
            float d0 = (r0 < NN) ? g_deg[r0] : 0.f;
            float d1 = (r1 < NN) ? g_deg[r1] : 0.f;
#pragma unroll
            for (int nt = 0; nt < 4; nt++) {
                int col = n0 + nt * 8 + 2 * tig;
                float* cc = acc[mt][nt];
                float bb0 = bias[col], bb1 = bias[col + 1];
                if (r0 < NN) { float2 v = {cc[0] + d0 * bb0, cc[1] + d0 * bb1}; *(float2*)(Og + (size_t)r0 * C + col) = v; }
                if (r1 < NN) { float2 v = {cc[2] + d1 * bb0, cc[3] + d1 * bb1}; *(float2*)(Og + (size_t)r1 * C + col) = v; }
            }
        }
    } else {
        // fused relu + L2 norm -> g_Hs (split pairs)
        __syncthreads();
#pragma unroll
        for (int mt = 0; mt < 4; mt++) {
            int r0 = i0 + m0 + mt * 16 + gid;
            int r1 = r0 + 8;
            int l0 = m0 + mt * 16 + gid, l1 = l0 + 8;
            float d0 = (r0 < NN) ? g_deg[r0] : 0.f;
            float d1 = (r1 < NN) ? g_deg[r1] : 0.f;
            float ss0 = 0.f, ss1 = 0.f;
#pragma unroll
            for (int nt = 0; nt < 4; nt++) {
                int col = n0 + nt * 8 + 2 * tig;
                float* cc = acc[mt][nt];
                float bb0 = bias[col], bb1 = bias[col + 1];
                cc[0] = fmaxf(cc[0] + d0 * bb0, 0.f);
                cc[1] = fmaxf(cc[1] + d0 * bb1, 0.f);
                cc[2] = fmaxf(cc[2] + d1 * bb0, 0.f);
                cc[3] = fmaxf(cc[3] + d1 * bb1, 0.f);
                ss0 += cc[0] * cc[0] + cc[1] * cc[1];
                ss1 += cc[2] * cc[2] + cc[3] * cc[3];
            }
            atomicAdd(&rowss[l0], ss0);
            atomicAdd(&rowss[l1], ss1);
        }
        __syncthreads();
#pragma unroll
        for (int mt = 0; mt < 4; mt++) {
            int r0 = i0 + m0 + mt * 16 + gid;
            int r1 = r0 + 8;
            int l0 = m0 + mt * 16 + gid, l1 = l0 + 8;
            float inv0 = 1.f / fmaxf(sqrtf(rowss[l0]), 1e-12f);
            float inv1 = 1.f / fmaxf(sqrtf(rowss[l1]), 1e-12f);
#pragma unroll
            for (int nt = 0; nt < 4; nt++) {
                int col = n0 + nt * 8 + 2 * tig;
                int P = (col >> 1);
                int off = pair_off_h(P);
                float* cc = acc[mt][nt];
                unsigned h, l;
                if (r0 < NN) {
                    split2(cc[0] * inv0, cc[1] * inv0, h, l);
                    g_Hs[(size_t)r0 * C + off] = h;
                    g_Hs[(size_t)r0 * C + off + 8] = l;
                }
                if (r1 < NN) {
                    split2(cc[2] * inv1, cc[3] * inv1, h, l);
                    g_Hs[(size_t)r1 * C + off] = h;
                    g_Hs[(size_t)r1 * C + off + 8] = l;
                }
            }
        }
    }
}

// ---------------- CSR edge aggregate + BN affine + split -------------------
__global__ __launch_bounds__(256) void edge_csr_kernel(int layer) {
    int node = (blockIdx.x * blockDim.x + threadIdx.x) >> 5;
    int lane = threadIdx.x & 31;
    if (node >= NN) return;
    int s0 = g_rowp[node], s1 = g_rowp[node + 1];
    float4 a = ((const float4*)(g_A + (size_t)node * C))[lane];
    float4 acc = make_float4(0.f, 0.f, 0.f, 0.f);
    int e = s0;
    for (; e + 3 < s1; e += 4) {
        int i0 = g_csr[e], i1 = g_csr[e + 1], i2 = g_csr[e + 2], i3 = g_csr[e + 3];
        float4 b0 = ((const float4*)(g_B + (size_t)i0 * C))[lane];
        float4 b1 = ((const float4*)(g_B + (size_t)i1 * C))[lane];
        float4 b2 = ((const float4*)(g_B + (size_t)i2 * C))[lane];
        float4 b3 = ((const float4*)(g_B + (size_t)i3 * C))[lane];
        acc.x += fmaxf(a.x + b0.x, 0.f) + fmaxf(a.x + b1.x, 0.f)
               + fmaxf(a.x + b2.x, 0.f) + fmaxf(a.x + b3.x, 0.f);
        acc.y += fmaxf(a.y + b0.y, 0.f) + fmaxf(a.y + b1.y, 0.f)
               + fmaxf(a.y + b2.y, 0.f) + fmaxf(a.y + b3.y, 0.f);
        acc.z += fmaxf(a.z + b0.z, 0.f) + fmaxf(a.z + b1.z, 0.f)
               + fmaxf(a.z + b2.z, 0.f) + fmaxf(a.z + b3.z, 0.f);
        acc.w += fmaxf(a.w + b0.w, 0.f) + fmaxf(a.w + b1.w, 0.f)
               + fmaxf(a.w + b2.w, 0.f) + fmaxf(a.w + b3.w, 0.f);
    }
    for (; e < s1; e++) {
        int sa = g_csr[e];
        float4 b0 = ((const float4*)(g_B + (size_t)sa * C))[lane];
        acc.x += fmaxf(a.x + b0.x, 0.f);
        acc.y += fmaxf(a.y + b0.y, 0.f);
        acc.z += fmaxf(a.z + b0.z, 0.f);
        acc.w += fmaxf(a.w + b0.w, 0.f);
    }
    float dg = (float)(s1 - s0);
    float4 sc = ((const float4*)(g_s[layer]))[lane];
    float4 cv = ((const float4*)(g_c[layer]))[lane];
    acc.x = sc.x * acc.x + dg * cv.x;
    acc.y = sc.y * acc.y + dg * cv.y;
    acc.z = sc.z * acc.z + dg * cv.z;
    acc.w = sc.w * acc.w + dg * cv.w;
    int P0 = lane * 2, P1 = lane * 2 + 1;
    int off0 = pair_off_h(P0), off1 = pair_off_h(P1);
    unsigned h, l;
    unsigned* o = g_Rs + (size_t)node * C;
    split2(acc.x, acc.y, h, l);
    o[off0] = h; o[off0 + 8] = l;
    split2(acc.z, acc.w, h, l);
    o[off1] = h; o[off1 + 8] = l;
    if (lane == 0) g_deg[node] = dg;
}

// ---------------- launch ----------------------------------------------------
extern "C" void kernel_launch(void* const* d_in, const int* in_sizes, int n_in,
                              void* d_out, int out_size) {
    const float* x   = (const float*)d_in[0];
    const void*  ei  = d_in[1];
    const float* w1a = (const float*)d_in[2];
    const float* b1a = (const float*)d_in[3];
    const float* g1  = (const float*)d_in[4];
    const float* be1 = (const float*)d_in[5];
    const float* rm1 = (const float*)d_in[6];
    const float* rv1 = (const float*)d_in[7];
    const float* w1b = (const float*)d_in[8];
    const float* b1b = (const float*)d_in[9];
    const float* w2a = (const float*)d_in[10];
    const float* b2a = (const float*)d_in[11];
    const float* g2  = (const float*)d_in[12];
    const float* be2 = (const float*)d_in[13];
    const float* rm2 = (const float*)d_in[14];
    const float* rv2 = (const float*)d_in[15];
    const float* w2b = (const float*)d_in[16];
    const float* b2b = (const float*)d_in[17];
    float* out = (float*)d_out;

    const int ROWB = (NN + 127) / 128;          // 391
    const int EB   = (NN * 32 + 255) / 256;     // 6250

    unsigned *Wf0, *Wf1, *Wbf0, *Wbf1;
    unsigned *Xs, *Hs, *Rs;
    cudaGetSymbolAddress((void**)&Xs, g_Xs);
    cudaGetSymbolAddress((void**)&Hs, g_Hs);
    cudaGetSymbolAddress((void**)&Rs, g_Rs);
    cudaGetSymbolAddress((void**)&Wf0, g_Wf);
    Wf1 = Wf0 + 2 * 16384;
    cudaGetSymbolAddress((void**)&Wbf0, g_Wbf);
    Wbf1 = Wbf0 + 16384;

    prep_all<<<256, 256>>>(w1a, w2a, w1b, w2b, g1, be1, rm1, rv1, g2, be2, rm2, rv2); // 0
    detect_kernel<<<1, 32>>>(ei);                                                     // 1
    conv_x<<<(NN * 8 + 255) / 256, 256>>>(x);                                         // 2
    // layer-1 AB GEMM at stream index 3 -> profiled by ncu
    mma_gemm<<<dim3(ROWB, 2), 256>>>(Xs, Wf0, b1a, nullptr, 0);                       // 3 -> g_A,g_B
    hist_kernel<<<(EE + 255) / 256, 256>>>(ei);                                       // 4
    scan_local<<<SCAN_NB, 256>>>();                                                   // 5
    scan_bsum<<<1, 256>>>();                                                          // 6
    scan_add<<<SCAN_NB, 256>>>();                                                     // 7
    scatter_kernel<<<(EE + 255) / 256, 256>>>(ei);                                    // 8

    // ---- layer 1 ----
    edge_csr_kernel<<<EB, 256>>>(0);                                                  // -> g_Rs,g_deg
    mma_gemm<<<dim3(ROWB, 1), 256>>>(Rs, Wbf0, b1b, nullptr, 2);                      // -> g_Hs

    // ---- layer 2 ----
    mma_gemm<<<dim3(ROWB, 2), 256>>>(Hs, Wf1, b2a, nullptr, 0);                       // g_Hs -> g_A,g_B
    edge_csr_kernel<<<EB, 256>>>(1);
    mma_gemm<<<dim3(ROWB, 1), 256>>>(Rs, Wbf1, b2b, out, 1);                          // -> d_out
}